// round 7
// baseline (speedup 1.0000x reference)
#include <cuda_runtime.h>
#include <cuda_bf16.h>
#include <cstdint>

// QuantumLSTM: T=1024, B=1024, IN=128, H=16.
// Single fused launch:
//   blocks 0..127    : consumers (LSTM recurrence), 8 warps = 8 batch rows each
//   blocks 128..8319 : producers (Z tile gemm), 8 blocks per timestep
// Producer->consumer handoff via per-t flags in global memory.

#define TT 1024
#define BB 1024
#define INDIM 128
#define HID 16
#define GD 64
#define DD 144
#define NROWS (TT * BB)
#define BPITCH 136     // bf16 elems per B smem row (272B, conflict-free for LDSM)
#define NCONS 128      // consumer blocks

__device__ float g_Z[(size_t)NROWS * GD];          // 256 MB scratch
__device__ int g_done[TT];                         // producer progress flags

__global__ void zero_flags() { g_done[threadIdx.x] = 0; }

// ---------------------------------------------------------------- helpers
static __device__ __forceinline__ void split2(float x, float y, uint32_t& hi, uint32_t& lo) {
    __nv_bfloat162 h2 = __floats2bfloat162_rn(x, y);
    hi = *(uint32_t*)&h2;
    __nv_bfloat162 l2 = __floats2bfloat162_rn(x - __bfloat162float(h2.x),
                                              y - __bfloat162float(h2.y));
    lo = *(uint32_t*)&l2;
}
static __device__ __forceinline__ void mma16816(float* acc, uint32_t a0, uint32_t a1,
                                                uint32_t a2, uint32_t a3,
                                                uint32_t b0, uint32_t b1) {
    asm volatile(
        "mma.sync.aligned.m16n8k16.row.col.f32.bf16.bf16.f32 "
        "{%0,%1,%2,%3},{%4,%5,%6,%7},{%8,%9},{%0,%1,%2,%3};"
        : "+f"(acc[0]), "+f"(acc[1]), "+f"(acc[2]), "+f"(acc[3])
        : "r"(a0), "r"(a1), "r"(a2), "r"(a3), "r"(b0), "r"(b1));
}
static __device__ __forceinline__ void ldsm4(uint32_t addr, uint32_t& r0, uint32_t& r1,
                                             uint32_t& r2, uint32_t& r3) {
    asm volatile("ldmatrix.sync.aligned.m8n8.x4.shared.b16 {%0,%1,%2,%3}, [%4];"
                 : "=r"(r0), "=r"(r1), "=r"(r2), "=r"(r3) : "r"(addr));
}
__device__ __forceinline__ float ex2f(float x) { float y; asm("ex2.approx.f32 %0, %1;" : "=f"(y) : "f"(x)); return y; }
__device__ __forceinline__ float rcpf(float x) { float y; asm("rcp.approx.f32 %0, %1;" : "=f"(y) : "f"(x)); return y; }

// ---------------------------------------------------------------- producer body
static __device__ void gemm_body(
    int tb, const float* __restrict__ A,
    const float* __restrict__ Wf, const float* __restrict__ bf, const float* __restrict__ tf,
    const float* __restrict__ Wi, const float* __restrict__ bi, const float* __restrict__ ti,
    const float* __restrict__ Wg, const float* __restrict__ bg, const float* __restrict__ tg,
    const float* __restrict__ Wo, const float* __restrict__ bo, const float* __restrict__ to_,
    char* sm) {
    __nv_bfloat16* Bh = (__nv_bfloat16*)sm;
    __nv_bfloat16* Bl = Bh + GD * BPITCH;
    float* bias_s = (float*)(Bl + GD * BPITCH);

    int tid = threadIdx.x;
    int warp = tid >> 5, lane = tid & 31;
    int qr = lane >> 2, qc = lane & 3;
    size_t row0 = (size_t)tb * 128;

#pragma unroll
    for (int i = 0; i < 4; i++) {
        int e = tid + 256 * i;
        int n = e >> 4, kq = (e & 15) * 8;
        int gate = n >> 4, j = n & 15;
        const float* W = (gate == 0) ? Wf : (gate == 1) ? Wi : (gate == 2) ? Wg : Wo;
        float4 u0 = *(const float4*)(W + j * DD + kq);
        float4 u1 = *(const float4*)(W + j * DD + kq + 4);
        uint32_t h[4], l[4];
        split2(u0.x, u0.y, h[0], l[0]);
        split2(u0.z, u0.w, h[1], l[1]);
        split2(u1.x, u1.y, h[2], l[2]);
        split2(u1.z, u1.w, h[3], l[3]);
        *(uint4*)(Bh + n * BPITCH + kq) = make_uint4(h[0], h[1], h[2], h[3]);
        *(uint4*)(Bl + n * BPITCH + kq) = make_uint4(l[0], l[1], l[2], l[3]);
    }
    if (tid < GD) {
        int gate = tid >> 4, j = tid & 15;
        const float* bp = (gate == 0) ? bf : (gate == 1) ? bi : (gate == 2) ? bg : bo;
        const float* tp = (gate == 0) ? tf : (gate == 1) ? ti : (gate == 2) ? tg : to_;
        bias_s[tid] = bp[j] + tp[j];
    }

    int tile = lane >> 3, rrow = lane & 7;
    uint32_t lrow_off = (uint32_t)(((tile >> 1) & 1) * 8 + rrow) * (BPITCH * 2) + (tile & 1) * 16;
    uint32_t bhb = (uint32_t)__cvta_generic_to_shared(Bh) + lrow_off;
    uint32_t blb = (uint32_t)__cvta_generic_to_shared(Bl) + lrow_off;

    const float* aptr = A + (row0 + warp * 16 + qr) * INDIM + qc * 2;

    float acc[8][4];
#pragma unroll
    for (int n = 0; n < 8; n++)
#pragma unroll
        for (int q = 0; q < 4; q++) acc[n][q] = 0.f;

    __syncthreads();

    float2 v[4], vn[4];
    v[0] = *(const float2*)(aptr);
    v[1] = *(const float2*)(aptr + 8 * INDIM);
    v[2] = *(const float2*)(aptr + 8);
    v[3] = *(const float2*)(aptr + 8 * INDIM + 8);

#pragma unroll
    for (int kk = 0; kk < 8; kk++) {
        if (kk < 7) {
            int k1 = (kk + 1) * 16;
            vn[0] = *(const float2*)(aptr + k1);
            vn[1] = *(const float2*)(aptr + 8 * INDIM + k1);
            vn[2] = *(const float2*)(aptr + k1 + 8);
            vn[3] = *(const float2*)(aptr + 8 * INDIM + k1 + 8);
        }
        uint32_t ah[4], al[4];
        split2(v[0].x, v[0].y, ah[0], al[0]);
        split2(v[1].x, v[1].y, ah[1], al[1]);
        split2(v[2].x, v[2].y, ah[2], al[2]);
        split2(v[3].x, v[3].y, ah[3], al[3]);

#pragma unroll
        for (int g = 0; g < 4; g++) {
            uint32_t koff = (uint32_t)(g * 16 * (BPITCH * 2) + kk * 32);
            uint32_t h0, h1, h2, h3, l0, l1, l2, l3;
            ldsm4(bhb + koff, h0, h1, h2, h3);
            ldsm4(blb + koff, l0, l1, l2, l3);
            mma16816(acc[2 * g],     ah[0], ah[1], ah[2], ah[3], h0, h1);
            mma16816(acc[2 * g + 1], ah[0], ah[1], ah[2], ah[3], h2, h3);
            mma16816(acc[2 * g],     al[0], al[1], al[2], al[3], h0, h1);
            mma16816(acc[2 * g + 1], al[0], al[1], al[2], al[3], h2, h3);
            mma16816(acc[2 * g],     ah[0], ah[1], ah[2], ah[3], l0, l1);
            mma16816(acc[2 * g + 1], ah[0], ah[1], ah[2], ah[3], l2, l3);
        }
#pragma unroll
        for (int q = 0; q < 4; q++) v[q] = vn[q];
    }

#pragma unroll
    for (int nt = 0; nt < 8; nt++) {
        int col = nt * 8 + qc * 2;
        float bias0 = bias_s[col], bias1 = bias_s[col + 1];
        size_t r1 = row0 + warp * 16 + qr;
        float2 v0 = make_float2(acc[nt][0] + bias0, acc[nt][1] + bias1);
        float2 v1 = make_float2(acc[nt][2] + bias0, acc[nt][3] + bias1);
        *(float2*)(g_Z + r1 * GD + col) = v0;
        *(float2*)(g_Z + (r1 + 8) * GD + col) = v1;
    }

    __threadfence();
    __syncthreads();
    if (tid == 0) atomicAdd(&g_done[tb >> 3], 1);
}

// ---------------------------------------------------------------- consumer body
// warp handles one batch element. Lanes 0-15: (f,i) unit j; lanes 16-31: (g,o) unit j.
static __device__ void lstm_body(
    int b, const float* __restrict__ Wf, const float* __restrict__ Wi,
    const float* __restrict__ Wg, const float* __restrict__ Wo,
    float* __restrict__ out) {
    const unsigned FULL = 0xffffffffu;
    int lane = threadIdx.x & 31;
    int g = lane & 15;
    bool hi2 = lane >= 16;
    int sbase = lane & 16;
    int eg = (g == 0) ? 15 : g;
    float cf = (g == 0) ? 2.f : 1.f;
    int src[15];
#pragma unroll
    for (int m = 1; m <= 15; m++) src[m - 1] = sbase | ((g - m) & 15);

    const float* WA = hi2 ? Wg : Wf;
    const float* WB = hi2 ? Wo : Wi;
    float wA[16], wB[16];
#pragma unroll
    for (int k = 0; k < 16; k++) {
        wA[k] = WA[g * DD + INDIM + k];
        wB[k] = WB[g * DD + INDIM + k];
    }

    float h = 0.f, c = 0.f;
    const float* zp = g_Z + (size_t)b * GD + lane + (hi2 ? 16 : 0);
    const size_t ts = (size_t)BB * GD;
    volatile int* df = g_done;

    while (df[0] != 8) __nanosleep(64);
    float z0 = __ldcg(zp), z1 = __ldcg(zp + 16);
    while (df[1] != 8) __nanosleep(64);
    float p0 = __ldcg(zp + ts), p1 = __ldcg(zp + ts + 16);
    const float* zpre = zp + 2 * ts;
    float* outp = out + (size_t)b * HID + g;

    for (int t = 0; t < TT; t++) {
        int tw = (t + 2 < TT) ? t + 2 : TT - 1;
        while (df[tw] != 8) __nanosleep(64);
        float n0 = __ldcg(zpre), n1 = __ldcg(zpre + 16);
        if (t + 3 < TT) zpre += ts;

        // h broadcast (independent shfls)
        float hk[16];
#pragma unroll
        for (int k = 0; k < 16; k++) hk[k] = __shfl_sync(FULL, h, k);

        // tree-form dot products, z seeded into first chain
        float a0, a1;
        {
            float q0 = fmaf(wA[0], hk[0], z0), q1 = wA[4] * hk[4], q2 = wA[8] * hk[8], q3 = wA[12] * hk[12];
            float r0 = fmaf(wB[0], hk[0], z1), r1 = wB[4] * hk[4], r2 = wB[8] * hk[8], r3 = wB[12] * hk[12];
#pragma unroll
            for (int k = 1; k < 4; k++) {
                q0 = fmaf(wA[k], hk[k], q0);           r0 = fmaf(wB[k], hk[k], r0);
                q1 = fmaf(wA[4 + k], hk[4 + k], q1);   r1 = fmaf(wB[4 + k], hk[4 + k], r1);
                q2 = fmaf(wA[8 + k], hk[8 + k], q2);   r2 = fmaf(wB[8 + k], hk[8 + k], r2);
                q3 = fmaf(wA[12 + k], hk[12 + k], q3); r3 = fmaf(wB[12 + k], hk[12 + k], r3);
            }
            a0 = (q0 + q1) + (q2 + q3);
            a1 = (r0 + r1) + (r2 + r3);
        }

        // qgate: sin then depth-1 scan (15 independent shfls + masked add tree).
        // q_g = cf*s_g + sum_{m<=eg} s_{(g-m)&15}; g=0 gets s_0 + total.
        float s0 = __sinf(a0), s1 = __sinf(a1);
        float va[15], vb[15];
#pragma unroll
        for (int m = 1; m <= 15; m++) {
            float x = __shfl_sync(FULL, s0, src[m - 1]);
            float y = __shfl_sync(FULL, s1, src[m - 1]);
            bool inc = (m <= eg);
            va[m - 1] = inc ? x : 0.f;
            vb[m - 1] = inc ? y : 0.f;
        }
        float q0, q1;
        {
            float t0 = cf * s0;
            float u0 = t0 + va[0],     u1 = va[1] + va[2],   u2 = va[3] + va[4],   u3 = va[5] + va[6];
            float u4 = va[7] + va[8],  u5 = va[9] + va[10],  u6 = va[11] + va[12], u7 = va[13] + va[14];
            q0 = ((u0 + u1) + (u2 + u3)) + ((u4 + u5) + (u6 + u7));
            float w0 = cf * s1;
            float x0 = w0 + vb[0],     x1 = vb[1] + vb[2],   x2 = vb[3] + vb[4],   x3 = vb[5] + vb[6];
            float x4 = vb[7] + vb[8],  x5 = vb[9] + vb[10],  x6 = vb[11] + vb[12], x7 = vb[13] + vb[14];
            q1 = ((x0 + x1) + (x2 + x3)) + ((x4 + x5) + (x6 + x7));
        }

        float scale0 = hi2 ? 2.885390082f : 1.442695041f;
        float r0 = rcpf(1.f + ex2f(-scale0 * q0));
        float act0 = hi2 ? (2.f * r0 - 1.f) : r0;            // tanh(g) / sigmoid(f)
        float act1 = rcpf(1.f + ex2f(-1.442695041f * q1));   // sigmoid(o) / sigmoid(i)

        float gg = __shfl_xor_sync(FULL, act0, 16);
        float oo = __shfl_xor_sync(FULL, act1, 16);

        c = fmaf(act0, c, act1 * gg);
        float th = 2.f * rcpf(1.f + ex2f(-2.885390082f * c)) - 1.f;
        h = oo * th;

        if (!hi2) *outp = h;
        outp += BB * HID;
        z0 = p0; z1 = p1; p0 = n0; p1 = n1;
    }
    if (!hi2) {
        out[(size_t)TT * BB * HID + (size_t)b * HID + g] = h;
        out[(size_t)TT * BB * HID + (size_t)BB * HID + (size_t)b * HID + g] = c;
    }
}

// ---------------------------------------------------------------- fused kernel
__global__ __launch_bounds__(256) void fused_kernel(
    const float* __restrict__ A,
    const float* __restrict__ Wf, const float* __restrict__ bf, const float* __restrict__ tf,
    const float* __restrict__ Wi, const float* __restrict__ bi, const float* __restrict__ ti,
    const float* __restrict__ Wg, const float* __restrict__ bg, const float* __restrict__ tg,
    const float* __restrict__ Wo, const float* __restrict__ bo, const float* __restrict__ to_,
    float* __restrict__ out) {
    __shared__ char sm[GD * BPITCH * 4 + GD * 4];
    if (blockIdx.x < NCONS) {
        int b = blockIdx.x * 8 + (threadIdx.x >> 5);
        lstm_body(b, Wf, Wi, Wg, Wo, out);
    } else {
        gemm_body(blockIdx.x - NCONS, A, Wf, bf, tf, Wi, bi, ti,
                  Wg, bg, tg, Wo, bo, to_, sm);
    }
}

// ---------------------------------------------------------------- launch
extern "C" void kernel_launch(void* const* d_in, const int* in_sizes, int n_in,
                              void* d_out, int out_size) {
    const float* inputs = (const float*)d_in[0];
    const float* Wf = (const float*)d_in[1];
    const float* bf = (const float*)d_in[2];
    const float* tf = (const float*)d_in[3];
    const float* Wi = (const float*)d_in[4];
    const float* bi = (const float*)d_in[5];
    const float* ti = (const float*)d_in[6];
    const float* Wg = (const float*)d_in[7];
    const float* bg = (const float*)d_in[8];
    const float* tg = (const float*)d_in[9];
    const float* Wo = (const float*)d_in[10];
    const float* bo = (const float*)d_in[11];
    const float* to_ = (const float*)d_in[12];
    float* out = (float*)d_out;

    zero_flags<<<1, TT>>>();
    fused_kernel<<<NCONS + NROWS / 128, 256>>>(inputs, Wf, bf, tf, Wi, bi, ti,
                                               Wg, bg, tg, Wo, bo, to_, out);
}